// round 13
// baseline (speedup 1.0000x reference)
#include <cuda_runtime.h>
#include <cuda_fp16.h>
#include <cstdint>

// ----------------------------------------------------------------------------
// Problem dims (fixed by dataset)
// ----------------------------------------------------------------------------
#define MDIM 8192   // B*S rows
#define NDIM 4096   // reduction dim
#define KDIM 4096   // output features
#define NGROUPS 32

// GEMM tiling (R12-proven): CTA 128x128, 8 warps (2 wm x 4 wn), warp 64x32.
// TWO CTAs per SM. fp16 m16n8k16, chunk 64, 3-stage / 1-sync pipeline.
#define TILE_M  128
#define TILE_KO 128
#define THREADS 256
#define CHUNK   64
#define STAGES  3
#define NCHUNK  (NDIM / CHUNK)   // 64

// Smem rows: 64 halves data + 8 pad = 144 B = 36 words. 36 mod 32 = 4 ->
// ldmatrix 8-row groups hit all 32 banks exactly once. Conflict-free.
#define ROW_BYTES  144
#define ROW_WORDS  36
#define SA_WORDS (TILE_M  * ROW_WORDS)        // 4608
#define SB_WORDS (TILE_KO * ROW_WORDS)        // 4608
#define STAGE_WORDS (SA_WORDS + SB_WORDS)     // 9216
#define SMEM_BYTES (STAGES * STAGE_WORDS * 4) // 110592/CTA -> 2 CTAs/SM

// In-GEMM prep: 148 wave-1 CTAs sweep 16 column-stripes of 256 cols.
#define PREP_CTAS 148
#define NSTRIPES  16
#define STRIPE_COLS 256

// ----------------------------------------------------------------------------
// Device scratch + progress flags (allocation-free rule: __device__ globals)
// ----------------------------------------------------------------------------
__device__ __half g_Wh[(size_t)KDIM * NDIM];  // 32 MB dequant W, fp16-RN
__device__ __half g_Xh[(size_t)MDIM * NDIM];  // 67 MB X, fp16-RN
__device__ int g_stripe_cnt[NSTRIPES];
__device__ int g_frontier;

// ----------------------------------------------------------------------------
// Helpers
// ----------------------------------------------------------------------------
__device__ __forceinline__ uint32_t smem_u32(const void* p) {
    uint32_t a;
    asm("{ .reg .u64 t; cvta.to.shared.u64 t, %1; cvt.u32.u64 %0, t; }"
        : "=r"(a) : "l"(p));
    return a;
}

__device__ __forceinline__ void cp_async16(uint32_t sdst, const void* gsrc) {
    asm volatile("cp.async.cg.shared.global [%0], [%1], 16;"
                 :: "r"(sdst), "l"(gsrc) : "memory");
}

__device__ __forceinline__ void ldsm_x4(uint32_t* r, uint32_t addr) {
    asm volatile("ldmatrix.sync.aligned.m8n8.x4.shared.b16 {%0,%1,%2,%3}, [%4];"
                 : "=r"(r[0]), "=r"(r[1]), "=r"(r[2]), "=r"(r[3])
                 : "r"(addr));
}

__device__ __forceinline__ void mma_f16(float* d, const uint32_t* a,
                                        const uint32_t* b) {
    asm volatile(
        "mma.sync.aligned.m16n8k16.row.col.f32.f16.f16.f32 "
        "{%0,%1,%2,%3}, {%4,%5,%6,%7}, {%8,%9}, {%0,%1,%2,%3};"
        : "+f"(d[0]), "+f"(d[1]), "+f"(d[2]), "+f"(d[3])
        : "r"(a[0]), "r"(a[1]), "r"(a[2]), "r"(a[3]), "r"(b[0]), "r"(b[1]));
}

__device__ __forceinline__ uint32_t pack_h2(float lo, float hi) {
    __half2 h = __halves2half2(__float2half_rn(lo), __float2half_rn(hi));
    return *reinterpret_cast<uint32_t*>(&h);
}

__device__ __forceinline__ int ld_acquire(const int* p) {
    int v;
    asm volatile("ld.global.acquire.gpu.b32 %0, [%1];"
                 : "=r"(v) : "l"(p) : "memory");
    return v;
}

// ----------------------------------------------------------------------------
// Kernel 1: reset progress flags (graph replays must start clean)
// ----------------------------------------------------------------------------
__global__ void reset_kernel() {
    if (threadIdx.x < NSTRIPES) g_stripe_cnt[threadIdx.x] = 0;
    if (threadIdx.x == NSTRIPES) g_frontier = 0;
}

// ----------------------------------------------------------------------------
// Kernel 2: fused prep + fp16 mma.sync GEMM.
// CTAs bid<148 first dequantize W / convert X stripe-by-stripe (publishing a
// release frontier); all CTAs gate their cp.async chunks on the frontier.
// out[m,k] = sum_n X[m,n]*W[k,n] + bias[k]
// ----------------------------------------------------------------------------
__global__ void __launch_bounds__(THREADS, 2)
gemm_kernel(const int* __restrict__ Wq,
            const float* __restrict__ scales,
            const float* __restrict__ zeros,
            const float* __restrict__ mu1,
            const float* __restrict__ mu2,
            const float* __restrict__ x,
            const float* __restrict__ bias,
            float* __restrict__ out) {
    extern __shared__ uint32_t smem[];

    const int tid = threadIdx.x;
    const int bid = blockIdx.x + gridDim.x * blockIdx.y;

    // ---- phase 1: distributed prep (wave-1 CTAs only) ----
    if (bid < PREP_CTAS) {
        for (int s = 0; s < NSTRIPES; s++) {
            const int colbase = s * STRIPE_COLS;
            // W rows r = bid + 148k, k<28 : dequant (scales/zeros/mu2/mu1)
            #pragma unroll
            for (int it = 0; it < 7; it++) {
                int idx = tid + it * THREADS;
                int k = idx >> 6;
                int r = bid + PREP_CTAS * k;
                int col = colbase + (idx & 63) * 4;
                if (r < KDIM) {
                    int4 q = *reinterpret_cast<const int4*>(
                        Wq + (size_t)r * NDIM + col);
                    int gg = col >> 7;
                    float sc = scales[r * NGROUPS + gg] * mu2[r];
                    float z = zeros[r * NGROUPS + gg];
                    float4 m1 = *reinterpret_cast<const float4*>(mu1 + col);
                    uint2 o;
                    o.x = pack_h2(((float)q.x - z) * sc * m1.x,
                                  ((float)q.y - z) * sc * m1.y);
                    o.y = pack_h2(((float)q.z - z) * sc * m1.z,
                                  ((float)q.w - z) * sc * m1.w);
                    *reinterpret_cast<uint2*>(g_Wh + (size_t)r * NDIM + col) = o;
                }
            }
            // X rows r = bid + 148k, k<56 : fp32 -> fp16
            #pragma unroll
            for (int it = 0; it < 14; it++) {
                int idx = tid + it * THREADS;
                int k = idx >> 6;
                int r = bid + PREP_CTAS * k;
                int col = colbase + (idx & 63) * 4;
                if (r < MDIM) {
                    float4 v = *reinterpret_cast<const float4*>(
                        x + (size_t)r * NDIM + col);
                    uint2 o;
                    o.x = pack_h2(v.x, v.y);
                    o.y = pack_h2(v.z, v.w);
                    *reinterpret_cast<uint2*>(g_Xh + (size_t)r * NDIM + col) = o;
                }
            }
            __threadfence();
            __syncthreads();
            if (tid == 0) {
                int old = atomicAdd(&g_stripe_cnt[s], 1);
                if (old == PREP_CTAS - 1) {
                    __threadfence();
                    atomicExch(&g_frontier, s + 1);   // release via fences
                }
            }
        }
    }

    // ---- phase 2: GEMM (R12-identical body, frontier-gated issues) ----
    const int wid = tid >> 5;
    const int lane = tid & 31;
    const int g = lane >> 2;
    const int c = lane & 3;
    const int wm = wid & 1;       // warp row (64 rows)
    const int wn = wid >> 1;      // warp col 0..3 (32 cols each)
    const int skew = ((wid >> 2) & 1) << 1;

    const int k0 = blockIdx.x * TILE_KO;
    const int m0 = blockIdx.y * TILE_M;

    float acc[4][4][4];
    #pragma unroll
    for (int mi = 0; mi < 4; mi++)
        #pragma unroll
        for (int nj = 0; nj < 4; nj++)
            #pragma unroll
            for (int r = 0; r < 4; r++) acc[mi][nj][r] = 0.f;

    const uint32_t smem_base = smem_u32(smem);

    const uint32_t laneA_off = (uint32_t)(lane & 15) * ROW_BYTES
                             + (uint32_t)((lane >> 4) & 1) * 16;
    const uint32_t laneB_off = ((uint32_t)(lane & 7)
                             + (uint32_t)((lane >> 4) & 1) * 8) * ROW_BYTES
                             + (uint32_t)((lane >> 3) & 1) * 16;

    int fseen = 0;   // stripes known complete (uniform across CTA)
    auto wait_stripe = [&](int need) {
        if (fseen >= need) return;
        if (tid == 0) {
            while (ld_acquire(&g_frontier) < need) __nanosleep(256);
        }
        __syncthreads();
        fseen = need;
    };

    auto issue = [&](int chunk, int buf) {
        const size_t n0 = (size_t)chunk * CHUNK;
        const uint32_t sA = smem_base + buf * STAGE_WORDS * 4;
        const uint32_t sB = sA + SA_WORDS * 4;
        #pragma unroll
        for (int i = 0; i < 4; i++) {            // A: 128 rows x 8 x 16B
            int id = tid + i * THREADS;
            int row = id >> 3, cc = id & 7;
            cp_async16(sA + row * ROW_BYTES + cc * 16,
                       g_Xh + (size_t)(m0 + row) * NDIM + n0 + cc * 8);
        }
        #pragma unroll
        for (int i = 0; i < 4; i++) {            // B: 128 rows x 8 x 16B
            int id = tid + i * THREADS;
            int row = id >> 3, cc = id & 7;
            cp_async16(sB + row * ROW_BYTES + cc * 16,
                       g_Wh + (size_t)(k0 + row) * NDIM + n0 + cc * 8);
        }
        asm volatile("cp.async.commit_group;" ::: "memory");
    };

    auto compute = [&](int buf) {
        const uint32_t sA = smem_base + buf * STAGE_WORDS * 4
                          + (wm * 64) * ROW_BYTES + laneA_off;
        const uint32_t sB = smem_base + (buf * STAGE_WORDS + SA_WORDS) * 4
                          + (wn * 32) * ROW_BYTES + laneB_off;
        #pragma unroll
        for (int ksi = 0; ksi < 4; ksi++) {
            const int ks = ksi ^ skew;
            uint32_t a[4][4], b[4][2];
            #pragma unroll
            for (int mi = 0; mi < 4; mi++)
                ldsm_x4(a[mi], sA + mi * 16 * ROW_BYTES + ks * 32);
            #pragma unroll
            for (int p = 0; p < 2; p++) {
                uint32_t r[4];
                ldsm_x4(r, sB + p * 16 * ROW_BYTES + ks * 32);
                b[2 * p + 0][0] = r[0];  b[2 * p + 0][1] = r[1];
                b[2 * p + 1][0] = r[2];  b[2 * p + 1][1] = r[3];
            }
            #pragma unroll
            for (int mi = 0; mi < 4; mi++)
                #pragma unroll
                for (int nj = 0; nj < 4; nj++)
                    mma_f16(acc[mi][nj], a[mi], b[nj]);
        }
    };

    // ---- pipeline: 3 stages, ONE sync per chunk, frontier-gated ----
    wait_stripe(1);                 // stripe 0 covers chunks 0..3
    issue(0, 0);
    issue(1, 1);
    for (int i = 0; i < NCHUNK; i++) {
        if (i < NCHUNK - 1)
            asm volatile("cp.async.wait_group 1;" ::: "memory");
        else
            asm volatile("cp.async.wait_group 0;" ::: "memory");
        __syncthreads();
        if (i + 2 < NCHUNK) {
            wait_stripe(((i + 2) >> 2) + 1);
            issue(i + 2, (i + 2) % STAGES);
        }
        compute(i % STAGES);
    }

    // ---- epilogue: bias + float2 stores ----
    #pragma unroll
    for (int nj = 0; nj < 4; nj++) {
        const int col = k0 + wn * 32 + nj * 8 + 2 * c;
        const float2 bv = *reinterpret_cast<const float2*>(bias + col);
        #pragma unroll
        for (int mi = 0; mi < 4; mi++) {
            const int row0 = m0 + wm * 64 + mi * 16 + g;
            float2 v0, v1;
            v0.x = acc[mi][nj][0] + bv.x;  v0.y = acc[mi][nj][1] + bv.y;
            v1.x = acc[mi][nj][2] + bv.x;  v1.y = acc[mi][nj][3] + bv.y;
            *reinterpret_cast<float2*>(out + (size_t)row0 * KDIM + col) = v0;
            *reinterpret_cast<float2*>(out + (size_t)(row0 + 8) * KDIM + col) = v1;
        }
    }
}

// ----------------------------------------------------------------------------
// Host launch
// ----------------------------------------------------------------------------
extern "C" void kernel_launch(void* const* d_in, const int* in_sizes, int n_in,
                              void* d_out, int out_size) {
    const float* x      = (const float*)d_in[0];
    const int*   Wq     = (const int*)d_in[1];
    const float* scales = (const float*)d_in[2];
    const float* zeros  = (const float*)d_in[3];
    const float* mu1    = (const float*)d_in[4];
    const float* mu2    = (const float*)d_in[5];
    const float* bias   = (const float*)d_in[6];
    float* out = (float*)d_out;

    reset_kernel<<<1, 32>>>();

    cudaFuncSetAttribute(gemm_kernel,
                         cudaFuncAttributeMaxDynamicSharedMemorySize,
                         SMEM_BYTES);
    dim3 grid(KDIM / TILE_KO, MDIM / TILE_M);   // (32, 64)
    gemm_kernel<<<grid, THREADS, SMEM_BYTES>>>(Wq, scales, zeros, mu1, mu2,
                                               x, bias, out);
}

// round 14
// speedup vs baseline: 1.0595x; 1.0595x over previous
#include <cuda_runtime.h>
#include <cuda_fp16.h>
#include <cstdint>

// ----------------------------------------------------------------------------
// Problem dims (fixed by dataset)
// ----------------------------------------------------------------------------
#define MDIM 8192   // B*S rows
#define NDIM 4096   // reduction dim
#define KDIM 4096   // output features
#define NGROUPS 32

// GEMM tiling (R12-proven): CTA 128x128, 8 warps (2 wm x 4 wn), warp 64x32.
// TWO CTAs per SM. fp16 m16n8k16, chunk 64, 3-stage / 1-sync pipeline.
#define TILE_M  128
#define TILE_KO 128
#define THREADS 256
#define CHUNK   64
#define STAGES  3
#define NCHUNK  (NDIM / CHUNK)   // 64

// Smem rows: 64 halves data + 8 pad = 144 B = 36 words. 36 mod 32 = 4 ->
// ldmatrix 8-row groups hit all 32 banks exactly once. Conflict-free.
#define ROW_BYTES  144
#define ROW_WORDS  36
#define SA_WORDS (TILE_M  * ROW_WORDS)        // 4608
#define SB_WORDS (TILE_KO * ROW_WORDS)        // 4608
#define STAGE_WORDS (SA_WORDS + SB_WORDS)     // 9216
#define SMEM_BYTES (STAGES * STAGE_WORDS * 4) // 110592/CTA -> 2 CTAs/SM

// Balanced prep: W blocks ~24KB traffic each; X blocks 4 float4/thread (~25KB).
#define XBLOCKS 8192
#define XV_PER_THREAD 4    // 8192*256*4 = 8388608 = MDIM*NDIM/4 float4s

// ----------------------------------------------------------------------------
// Device scratch (allocation-free rule: __device__ globals)
// ----------------------------------------------------------------------------
__device__ __half g_Wh[(size_t)KDIM * NDIM];  // 32 MB dequant W, fp16-RN
__device__ __half g_Xh[(size_t)MDIM * NDIM];  // 67 MB X, fp16-RN

// ----------------------------------------------------------------------------
// Helpers
// ----------------------------------------------------------------------------
__device__ __forceinline__ uint32_t smem_u32(const void* p) {
    uint32_t a;
    asm("{ .reg .u64 t; cvta.to.shared.u64 t, %1; cvt.u32.u64 %0, t; }"
        : "=r"(a) : "l"(p));
    return a;
}

__device__ __forceinline__ void cp_async16(uint32_t sdst, const void* gsrc) {
    asm volatile("cp.async.cg.shared.global [%0], [%1], 16;"
                 :: "r"(sdst), "l"(gsrc) : "memory");
}

__device__ __forceinline__ void ldsm_x4(uint32_t* r, uint32_t addr) {
    asm volatile("ldmatrix.sync.aligned.m8n8.x4.shared.b16 {%0,%1,%2,%3}, [%4];"
                 : "=r"(r[0]), "=r"(r[1]), "=r"(r[2]), "=r"(r[3])
                 : "r"(addr));
}

__device__ __forceinline__ void mma_f16(float* d, const uint32_t* a,
                                        const uint32_t* b) {
    asm volatile(
        "mma.sync.aligned.m16n8k16.row.col.f32.f16.f16.f32 "
        "{%0,%1,%2,%3}, {%4,%5,%6,%7}, {%8,%9}, {%0,%1,%2,%3};"
        : "+f"(d[0]), "+f"(d[1]), "+f"(d[2]), "+f"(d[3])
        : "r"(a[0]), "r"(a[1]), "r"(a[2]), "r"(a[3]), "r"(b[0]), "r"(b[1]));
}

__device__ __forceinline__ uint32_t pack_h2(float lo, float hi) {
    __half2 h = __halves2half2(__float2half_rn(lo), __float2half_rn(hi));
    return *reinterpret_cast<uint32_t*>(&h);
}

// ----------------------------------------------------------------------------
// Kernel 1 (merged, balanced): blocks [0, KDIM) dequantize W rows; blocks
// [KDIM, KDIM+XBLOCKS) convert X to fp16. One launch, balanced block sizes.
// ----------------------------------------------------------------------------
__global__ void prep_kernel(const int* __restrict__ Wq,
                            const float* __restrict__ scales,
                            const float* __restrict__ zeros,
                            const float* __restrict__ mu1,
                            const float* __restrict__ mu2,
                            const float* __restrict__ x) {
    if (blockIdx.x < KDIM) {
        int k = blockIdx.x;
        float m2 = mu2[k];
        const int4* wrow = reinterpret_cast<const int4*>(Wq + (size_t)k * NDIM);
        uint2* drow = reinterpret_cast<uint2*>(g_Wh + (size_t)k * NDIM);
        for (int n4 = threadIdx.x; n4 < NDIM / 4; n4 += blockDim.x) {
            int n = n4 * 4;
            int g = n >> 7;
            float s = scales[k * NGROUPS + g] * m2;
            float z = zeros[k * NGROUPS + g];
            int4 q = wrow[n4];
            uint2 o;
            o.x = pack_h2(((float)q.x - z) * s * mu1[n + 0],
                          ((float)q.y - z) * s * mu1[n + 1]);
            o.y = pack_h2(((float)q.z - z) * s * mu1[n + 2],
                          ((float)q.w - z) * s * mu1[n + 3]);
            drow[n4] = o;
        }
    } else {
        const float4* xi = reinterpret_cast<const float4*>(x);
        uint2* xo = reinterpret_cast<uint2*>(g_Xh);
        size_t base = (size_t)(blockIdx.x - KDIM) * blockDim.x + threadIdx.x;
        const size_t stride = (size_t)XBLOCKS * blockDim.x;
        #pragma unroll
        for (int j = 0; j < XV_PER_THREAD; j++) {
            size_t i = base + (size_t)j * stride;
            float4 v = xi[i];
            uint2 o;
            o.x = pack_h2(v.x, v.y);
            o.y = pack_h2(v.z, v.w);
            xo[i] = o;
        }
    }
}

// ----------------------------------------------------------------------------
// Kernel 2: fp16 mma.sync GEMM (R12-identical body) + PDL entry gate.
// out[m,k] = sum_n X[m,n]*W[k,n] + bias[k]
// ----------------------------------------------------------------------------
__global__ void __launch_bounds__(THREADS, 2)
gemm_kernel(const float* __restrict__ bias, float* __restrict__ out) {
    // PDL: CTAs are pre-launched while prep drains; wait gates data reads.
    asm volatile("griddepcontrol.wait;" ::: "memory");

    extern __shared__ uint32_t smem[];

    const int tid = threadIdx.x;
    const int wid = tid >> 5;
    const int lane = tid & 31;
    const int g = lane >> 2;      // 0..7 (epilogue row group)
    const int c = lane & 3;       // 0..3
    const int wm = wid & 1;       // warp row (64 rows)
    const int wn = wid >> 1;      // warp col 0..3 (32 cols each)
    const int skew = ((wid >> 2) & 1) << 1;   // 0 or 2 (of 4 k-steps)

    const int k0 = blockIdx.x * TILE_KO;
    const int m0 = blockIdx.y * TILE_M;

    float acc[4][4][4];           // [mi][nj][frag] = 64 regs
    #pragma unroll
    for (int mi = 0; mi < 4; mi++)
        #pragma unroll
        for (int nj = 0; nj < 4; nj++)
            #pragma unroll
            for (int r = 0; r < 4; r++) acc[mi][nj][r] = 0.f;

    const uint32_t smem_base = smem_u32(smem);

    // ldmatrix lane-dependent offsets (bytes), round-9 proven mapping.
    const uint32_t laneA_off = (uint32_t)(lane & 15) * ROW_BYTES
                             + (uint32_t)((lane >> 4) & 1) * 16;
    const uint32_t laneB_off = ((uint32_t)(lane & 7)
                             + (uint32_t)((lane >> 4) & 1) * 8) * ROW_BYTES
                             + (uint32_t)((lane >> 3) & 1) * 16;

    // ---- async copy of one chunk (64 halves = 128B data per row) ----
    auto issue = [&](int chunk, int buf) {
        const size_t n0 = (size_t)chunk * CHUNK;
        const uint32_t sA = smem_base + buf * STAGE_WORDS * 4;
        const uint32_t sB = sA + SA_WORDS * 4;
        #pragma unroll
        for (int i = 0; i < 4; i++) {            // A: 128 rows x 8 x 16B
            int id = tid + i * THREADS;
            int row = id >> 3, cc = id & 7;
            cp_async16(sA + row * ROW_BYTES + cc * 16,
                       g_Xh + (size_t)(m0 + row) * NDIM + n0 + cc * 8);
        }
        #pragma unroll
        for (int i = 0; i < 4; i++) {            // B: 128 rows x 8 x 16B
            int id = tid + i * THREADS;
            int row = id >> 3, cc = id & 7;
            cp_async16(sB + row * ROW_BYTES + cc * 16,
                       g_Wh + (size_t)(k0 + row) * NDIM + n0 + cc * 8);
        }
        asm volatile("cp.async.commit_group;" ::: "memory");
    };

    // ---- compute one chunk: 4 k16-steps via ldmatrix ----
    auto compute = [&](int buf) {
        const uint32_t sA = smem_base + buf * STAGE_WORDS * 4
                          + (wm * 64) * ROW_BYTES + laneA_off;
        const uint32_t sB = smem_base + (buf * STAGE_WORDS + SA_WORDS) * 4
                          + (wn * 32) * ROW_BYTES + laneB_off;
        #pragma unroll
        for (int ksi = 0; ksi < 4; ksi++) {
            const int ks = ksi ^ skew;
            uint32_t a[4][4], b[4][2];
            #pragma unroll
            for (int mi = 0; mi < 4; mi++)
                ldsm_x4(a[mi], sA + mi * 16 * ROW_BYTES + ks * 32);
            #pragma unroll
            for (int p = 0; p < 2; p++) {        // two n8 tiles per ldmatrix
                uint32_t r[4];
                ldsm_x4(r, sB + p * 16 * ROW_BYTES + ks * 32);
                b[2 * p + 0][0] = r[0];  b[2 * p + 0][1] = r[1];
                b[2 * p + 1][0] = r[2];  b[2 * p + 1][1] = r[3];
            }
            #pragma unroll
            for (int mi = 0; mi < 4; mi++)
                #pragma unroll
                for (int nj = 0; nj < 4; nj++)
                    mma_f16(acc[mi][nj], a[mi], b[nj]);
        }
    };

    // ---- pipeline: 3 stages, ONE sync per chunk ----
    // Safety: issue(i+2) writes buf (i+2)%3, last read by compute(i-1)
    // [(i-1)%3 == (i+2)%3], separated by the top-of-loop __syncthreads().
    issue(0, 0);
    issue(1, 1);
    for (int i = 0; i < NCHUNK; i++) {
        if (i < NCHUNK - 1)
            asm volatile("cp.async.wait_group 1;" ::: "memory");
        else
            asm volatile("cp.async.wait_group 0;" ::: "memory");
        __syncthreads();
        if (i + 2 < NCHUNK) issue(i + 2, (i + 2) % STAGES);
        compute(i % STAGES);
    }

    // ---- epilogue: bias + float2 stores ----
    #pragma unroll
    for (int nj = 0; nj < 4; nj++) {
        const int col = k0 + wn * 32 + nj * 8 + 2 * c;
        const float2 bv = *reinterpret_cast<const float2*>(bias + col);
        #pragma unroll
        for (int mi = 0; mi < 4; mi++) {
            const int row0 = m0 + wm * 64 + mi * 16 + g;
            float2 v0, v1;
            v0.x = acc[mi][nj][0] + bv.x;  v0.y = acc[mi][nj][1] + bv.y;
            v1.x = acc[mi][nj][2] + bv.x;  v1.y = acc[mi][nj][3] + bv.y;
            *reinterpret_cast<float2*>(out + (size_t)row0 * KDIM + col) = v0;
            *reinterpret_cast<float2*>(out + (size_t)(row0 + 8) * KDIM + col) = v1;
        }
    }
}

// ----------------------------------------------------------------------------
// Host launch
// ----------------------------------------------------------------------------
extern "C" void kernel_launch(void* const* d_in, const int* in_sizes, int n_in,
                              void* d_out, int out_size) {
    const float* x      = (const float*)d_in[0];
    const int*   Wq     = (const int*)d_in[1];
    const float* scales = (const float*)d_in[2];
    const float* zeros  = (const float*)d_in[3];
    const float* mu1    = (const float*)d_in[4];
    const float* mu2    = (const float*)d_in[5];
    const float* bias   = (const float*)d_in[6];
    float* out = (float*)d_out;

    prep_kernel<<<KDIM + XBLOCKS, 256>>>(Wq, scales, zeros, mu1, mu2, x);

    cudaFuncSetAttribute(gemm_kernel,
                         cudaFuncAttributeMaxDynamicSharedMemorySize,
                         SMEM_BYTES);

    // PDL launch: GEMM CTAs pre-launch while prep drains; griddepcontrol.wait
    // inside the kernel gates consumption of prep's output.
    cudaLaunchConfig_t cfg = {};
    cfg.gridDim = dim3(KDIM / TILE_KO, MDIM / TILE_M);   // (32, 64)
    cfg.blockDim = dim3(THREADS, 1, 1);
    cfg.dynamicSmemBytes = SMEM_BYTES;
    cudaLaunchAttribute attrs[1];
    attrs[0].id = cudaLaunchAttributeProgrammaticStreamSerialization;
    attrs[0].val.programmaticStreamSerializationAllowed = 1;
    cfg.attrs = attrs;
    cfg.numAttrs = 1;
    cudaError_t err = cudaLaunchKernelEx(&cfg, gemm_kernel, bias, out);
    if (err != cudaSuccess) {
        // Fallback: plain serialized launch (identical semantics, no overlap)
        gemm_kernel<<<cfg.gridDim, cfg.blockDim, SMEM_BYTES>>>(bias, out);
    }
}